// round 14
// baseline (speedup 1.0000x reference)
#include <cuda_runtime.h>
#include <math.h>

#define NS 64          // coarse samples
#define NF 128         // fine samples
#define NC 192         // combined
#define RPB 16         // rays per block (16-lane subwarp per ray)
#define FULL 0xffffffffu

// #{k in [0,128) : u_k < x}, u_k = 0.05 + k * (0.9/127)
__device__ __forceinline__ int count_u(float x) {
    int c = __float2int_ru((x - 0.05f) * (127.0f / 0.9f));
    return min(max(c, 0), NF);
}

__device__ __forceinline__ unsigned long long pack2(float lo, float hi) {
    unsigned long long r;
    asm("mov.b64 %0, {%1, %2};" : "=l"(r) : "f"(lo), "f"(hi));
    return r;
}
__device__ __forceinline__ void unpack2(unsigned long long v, float& lo, float& hi) {
    asm("mov.b64 {%0, %1}, %2;" : "=f"(lo), "=f"(hi) : "l"(v));
}
__device__ __forceinline__ unsigned long long addp(unsigned long long a, unsigned long long b) {
    unsigned long long r;
    asm("add.rn.f32x2 %0, %1, %2;" : "=l"(r) : "l"(a), "l"(b));
    return r;
}

__global__ __launch_bounds__(256, 8)
void pdf_sampler_kernel(const float* __restrict__ near_, const float* __restrict__ far_,
                        const float* __restrict__ density, const float* __restrict__ rgb,
                        float* __restrict__ zs_out, float* __restrict__ rgb_out,
                        float* __restrict__ depth_out, float* __restrict__ acc_out,
                        int B)
{
    __shared__ __align__(16) float  s_z[RPB][NC];        // staging; first 128B alias byte-S[]
    __shared__ __align__(16) float2 s_par[RPB][NS + 2];  // (cb, g) per interval, + tail

    const int sub = threadIdx.x >> 4;    // ray slot in block
    const int g   = threadIdx.x & 15;    // lane within 16-lane group
    const int haf = (threadIdx.x >> 4) & 1;  // which half of the hw warp
    const int ray = blockIdx.x * RPB + sub;
    if (ray >= B) return;

    const float nr = near_[ray];
    const float fr = far_[ray];
    const float delta = (fr - nr) * (1.0f / NS);

    // ---- density: 4 elems per lane (float4, coalesced) ----
    const float4 dvec = *reinterpret_cast<const float4*>(density + (size_t)ray * NS + 4 * g);
    const float e0 = dvec.x * delta;
    const float e1 = dvec.y * delta;
    const float e2 = dvec.z * delta;
    const float e3 = dvec.w * delta;

    // ---- 16-wide inclusive prefix sum of optical depth (quad per lane) ----
    const float tot = ((e0 + e1) + e2) + e3;
    float s = tot;
    #pragma unroll
    for (int off = 1; off < 16; off <<= 1) {
        float v = __shfl_up_sync(FULL, s, off, 16);
        if (g >= off) s += v;
    }
    const float excl = s - tot;          // cum optical depth before elem 4*g

    // weights chain: w_i = T_i * (1 - exp(-e_i)), T_{i+1} = T_i - w_i
    const float T0 = __expf(-excl);
    const float w0 = T0 * (1.0f - __expf(-e0));
    const float T1 = T0 - w0;
    const float w1 = T1 * (1.0f - __expf(-e1));
    const float T2 = T1 - w1;
    const float w2 = T2 * (1.0f - __expf(-e2));
    const float T3 = T2 - w2;
    const float w3 = T3 * (1.0f - __expf(-e3));
    const float T4 = T3 - w3;

    // analytic mids
    const float m0 = fmaf((float)(4 * g) + 0.5f, delta, nr);
    const float m1 = m0 + delta;
    const float m2 = m1 + delta;
    const float m3 = m2 + delta;

    // ---- rgb loads: 12 contiguous floats per lane (3x float4) ----
    const float* rrow = rgb + (size_t)ray * (NS * 3) + 12 * g;
    const float4 f0 = *reinterpret_cast<const float4*>(rrow + 0);  // r0 g0 b0 r1
    const float4 f1 = *reinterpret_cast<const float4*>(rrow + 4);  // g1 b1 r2 g2
    const float4 f2 = *reinterpret_cast<const float4*>(rrow + 8);  // b2 r3 g3 b3

    // ---- reductions (packed f32x2 butterflies, width 16) ----
    const float rs = w0 * f0.x + w1 * f0.w + w2 * f1.z + w3 * f2.y;
    const float gs = w0 * f0.y + w1 * f1.x + w2 * f1.w + w3 * f2.z;
    const float bs = w0 * f0.z + w1 * f1.y + w2 * f2.x + w3 * f2.w;
    const float ds = w0 * m0 + w1 * m1 + w2 * m2 + w3 * m3;
    unsigned long long q0 = pack2(rs, gs);
    unsigned long long q1 = pack2(bs, ds);
    #pragma unroll
    for (int off = 8; off >= 1; off >>= 1) {
        q0 = addp(q0, __shfl_xor_sync(FULL, q0, off, 16));
        q1 = addp(q1, __shfl_xor_sync(FULL, q1, off, 16));
    }

    // total weight: exp(-ctot) is group-lane-15's T4
    const float wsum = 1.0f - __shfl_sync(FULL, T4, 15, 16);
    const float inv  = __fdividef(1.0f, wsum + 1e-6f);

    // normalized cdf at this lane's four positions
    const float cA = (1.0f - T1) * inv;   // cdf[4g]
    const float cB = (1.0f - T2) * inv;   // cdf[4g+1]
    const float cC = (1.0f - T3) * inv;   // cdf[4g+2]
    const float cD = (1.0f - T4) * inv;   // cdf[4g+3]
    float cprev = __shfl_up_sync(FULL, cD, 1, 16);   // cdf[4g-1]
    if (g == 0) cprev = 0.0f;

    // interval ends in fine-sample index space
    const int ke[4] = { count_u(cA), count_u(cB), count_u(cC), count_u(cD) };
    int kS = __shfl_up_sync(FULL, ke[3], 1, 16);     // = count_u(cprev)
    if (g == 0) kS = 0;

    // per-interval affine params: z = fmaf(u - cb, gcoef, mids[pc-1])
    const float d0 = cA - cprev;
    const float g0c = (g == 0) ? 0.0f : ((d0 < 1e-5f) ? delta : __fdividef(delta, d0));
    const float d1 = cB - cA;
    const float g1c = (d1 < 1e-5f) ? delta : __fdividef(delta, d1);
    const float d2 = cC - cB;
    const float g2c = (d2 < 1e-5f) ? delta : __fdividef(delta, d2);
    const float d3 = cD - cC;
    const float g3c = (d3 < 1e-5f) ? delta : __fdividef(delta, d3);

    float* zw = s_z[sub];
    unsigned char* Sw = reinterpret_cast<unsigned char*>(zw);  // byte S[128] aliases staging
    float2* pw = s_par[sub];

    // ---- S init (8B/lane) + params (2x STS.128/lane) ----
    reinterpret_cast<unsigned long long*>(zw)[g] = 0ULL;
    reinterpret_cast<float4*>(pw)[2 * g]     = make_float4(cprev, g0c, cA, g1c);
    reinterpret_cast<float4*>(pw)[2 * g + 1] = make_float4(cB,    g2c, cC, g3c);
    if (g == 15) pw[NS] = make_float2(0.0f, 0.0f);   // tail p=64: z = mids[63]
    __syncwarp();
    // interval-start marks (nonempty intervals have distinct starts; bytes 0..64)
    if (kS    < ke[0]) Sw[kS]    = (unsigned char)(4 * g);
    if (ke[0] < ke[1]) Sw[ke[0]] = (unsigned char)(4 * g + 1);
    if (ke[1] < ke[2]) Sw[ke[1]] = (unsigned char)(4 * g + 2);
    if (ke[2] < ke[3]) Sw[ke[2]] = (unsigned char)(4 * g + 3);
    if (g == 15 && ke[3] < NF) Sw[ke[3]] = (unsigned char)NS;   // tail interval start
    __syncwarp();

    // ---- p(k): two 16-wide byte max-scans (block k<64 and k>=64) ----
    const unsigned int wlo = reinterpret_cast<const unsigned int*>(zw)[g];       // bytes 4g..4g+3
    const unsigned int whi = reinterpret_cast<const unsigned int*>(zw)[16 + g];  // bytes 64+4g..
    int r0[4], r1[4];
    {
        int a = 0, b = 0;
        #pragma unroll
        for (int j = 0; j < 4; ++j) {
            a = max(a, (int)((wlo >> (8 * j)) & 0xFFu));  r0[j] = a;
            b = max(b, (int)((whi >> (8 * j)) & 0xFFu));  r1[j] = b;
        }
    }
    int mm0 = r0[3], mm1 = r1[3];
    #pragma unroll
    for (int off = 1; off < 16; off <<= 1) {
        int t0 = __shfl_up_sync(FULL, mm0, off, 16);
        int t1 = __shfl_up_sync(FULL, mm1, off, 16);
        if (g >= off) { mm0 = max(mm0, t0); mm1 = max(mm1, t1); }
    }
    int pex0 = __shfl_up_sync(FULL, mm0, 1, 16);
    int pex1 = __shfl_up_sync(FULL, mm1, 1, 16);
    const int tot0 = __shfl_sync(FULL, mm0, 15, 16);
    if (g == 0) { pex0 = 0; pex1 = 0; }
    pex1 = max(pex1, tot0);
    __syncwarp();   // S fully consumed; staging reuse begins

    // ---- balanced fine pass: stride-4 mapping, halves phase-offset (jj = j^2) ----
    const float ustep = 0.9f / 127.0f;
    const float base  = nr - 0.5f * delta;       // mids[pc-1] = fmaf(pc, delta, base)
    #pragma unroll
    for (int j = 0; j < 4; ++j) {
        const int jj  = haf ? (j ^ 2) : j;
        const int rA  = haf ? r0[j ^ 2] : r0[j];
        const int rB  = haf ? r1[j ^ 2] : r1[j];

        const int kLo = 4 * g + jj;                  // block 0
        const int pLo = max(pex0, rA);
        const int cLo = min(max(pLo, 1), NS);
        const float2 qLo = pw[pLo];
        const float uLo  = fmaf((float)kLo, ustep, 0.05f);
        zw[kLo + cLo] = fmaf(uLo - qLo.x, qLo.y, fmaf((float)cLo, delta, base));

        const int kHi = 64 + kLo;                    // block 1
        const int pHi = max(pex1, rB);
        const int cHi = min(max(pHi, 1), NS);
        const float2 qHi = pw[pHi];
        const float uHi  = fmaf((float)kHi, ustep, 0.05f);
        zw[kHi + cHi] = fmaf(uHi - qHi.x, qHi.y, fmaf((float)cHi, delta, base));
    }

    // ---- mids (stride-4, halves phase-offset): slot = i + count_u(cdf[i]) ----
    {
        const float mv[4] = { m0, m1, m2, m3 };
        #pragma unroll
        for (int j = 0; j < 4; ++j) {
            const int jj   = haf ? (j ^ 2) : j;
            const float mj = haf ? mv[j ^ 2] : mv[j];
            const int  kkj = haf ? ke[j ^ 2] : ke[j];
            const int  i   = 4 * g + jj;
            zw[(i == 0) ? 0 : (i + kkj)] = mj;
        }
    }
    __syncwarp();

    // ---- coalesced vectorized write of the merged row (3 full float4 passes) ----
    float4* zv = reinterpret_cast<float4*>(zs_out + (size_t)ray * NC);
    const float4* sv = reinterpret_cast<const float4*>(zw);
    zv[g]      = sv[g];
    zv[16 + g] = sv[16 + g];
    zv[32 + g] = sv[32 + g];

    // ---- scalar outputs, distributed (all lanes hold reduced values) ----
    if (g < 5) {
        float rrs, rgs, rbs, rds;
        unpack2(q0, rrs, rgs);
        unpack2(q1, rbs, rds);
        if (g < 3) {
            const float val = (g == 0) ? rrs : (g == 1) ? rgs : rbs;
            rgb_out[(size_t)ray * 3 + g] = val;
        } else if (g == 3) {
            depth_out[ray] = __fdividef(rds, wsum + 1e-8f);
        } else {
            acc_out[ray] = wsum;
        }
    }
}

extern "C" void kernel_launch(void* const* d_in, const int* in_sizes, int n_in,
                              void* d_out, int out_size)
{
    const float* near_   = (const float*)d_in[0];
    const float* far_    = (const float*)d_in[1];
    const float* density = (const float*)d_in[2];
    const float* rgb     = (const float*)d_in[3];
    const int B = in_sizes[0];

    float* out   = (float*)d_out;
    float* zs    = out;                       // B * 192
    float* rgbo  = zs + (size_t)B * NC;       // B * 3
    float* depth = rgbo + (size_t)B * 3;      // B
    float* acc   = depth + B;                 // B

    const int blocks = (B + RPB - 1) / RPB;
    pdf_sampler_kernel<<<blocks, 256>>>(near_, far_, density, rgb,
                                        zs, rgbo, depth, acc, B);
}

// round 15
// speedup vs baseline: 1.1492x; 1.1492x over previous
#include <cuda_runtime.h>
#include <math.h>

#define NS 64          // coarse samples
#define NF 128         // fine samples
#define NC 192         // combined
#define RPB 16         // rays per block (16-lane subwarp per ray)
#define FULL 0xffffffffu

// #{k in [0,128) : u_k < x}, u_k = 0.05 + k * (0.9/127)
__device__ __forceinline__ int count_u(float x) {
    int c = __float2int_ru((x - 0.05f) * (127.0f / 0.9f));
    return min(max(c, 0), NF);
}

__device__ __forceinline__ unsigned long long pack2(float lo, float hi) {
    unsigned long long r;
    asm("mov.b64 %0, {%1, %2};" : "=l"(r) : "f"(lo), "f"(hi));
    return r;
}
__device__ __forceinline__ void unpack2(unsigned long long v, float& lo, float& hi) {
    asm("mov.b64 {%0, %1}, %2;" : "=f"(lo), "=f"(hi) : "l"(v));
}
__device__ __forceinline__ unsigned long long addp(unsigned long long a, unsigned long long b) {
    unsigned long long r;
    asm("add.rn.f32x2 %0, %1, %2;" : "=l"(r) : "l"(a), "l"(b));
    return r;
}

__global__ __launch_bounds__(256, 8)
void pdf_sampler_kernel(const float* __restrict__ near_, const float* __restrict__ far_,
                        const float* __restrict__ density, const float* __restrict__ rgb,
                        float* __restrict__ zs_out, float* __restrict__ rgb_out,
                        float* __restrict__ depth_out, float* __restrict__ acc_out,
                        int B)
{
    __shared__ __align__(16) float  s_z[RPB][NC];        // staging; first 128B/ray alias byte-S[]
    __shared__ __align__(16) float2 s_par[RPB][NS + 2];  // (cb, g) per interval, + tail

    const int sub = threadIdx.x >> 4;    // ray slot in block
    const int g   = threadIdx.x & 15;    // lane within 16-lane group
    const int ray = blockIdx.x * RPB + sub;

    if (ray < B) {
    const float nr = near_[ray];
    const float fr = far_[ray];
    const float delta = (fr - nr) * (1.0f / NS);

    // ---- density: 4 elems per lane (float4, coalesced) ----
    const float4 dvec = *reinterpret_cast<const float4*>(density + (size_t)ray * NS + 4 * g);
    const float e0 = dvec.x * delta;
    const float e1 = dvec.y * delta;
    const float e2 = dvec.z * delta;
    const float e3 = dvec.w * delta;

    // ---- 16-wide inclusive prefix sum of optical depth (quad per lane) ----
    const float tot = ((e0 + e1) + e2) + e3;
    float s = tot;
    #pragma unroll
    for (int off = 1; off < 16; off <<= 1) {
        float v = __shfl_up_sync(FULL, s, off, 16);
        if (g >= off) s += v;
    }
    const float excl = s - tot;          // cum optical depth before elem 4*g

    // weights chain: w_i = T_i * (1 - exp(-e_i)), T_{i+1} = T_i - w_i
    const float T0 = __expf(-excl);
    const float w0 = T0 * (1.0f - __expf(-e0));
    const float T1 = T0 - w0;
    const float w1 = T1 * (1.0f - __expf(-e1));
    const float T2 = T1 - w1;
    const float w2 = T2 * (1.0f - __expf(-e2));
    const float T3 = T2 - w2;
    const float w3 = T3 * (1.0f - __expf(-e3));
    const float T4 = T3 - w3;

    // analytic mids
    const float m0 = fmaf((float)(4 * g) + 0.5f, delta, nr);
    const float m1 = m0 + delta;
    const float m2 = m1 + delta;
    const float m3 = m2 + delta;

    // ---- rgb loads: 12 contiguous floats per lane (3x float4) ----
    const float* rrow = rgb + (size_t)ray * (NS * 3) + 12 * g;
    const float4 f0 = *reinterpret_cast<const float4*>(rrow + 0);  // r0 g0 b0 r1
    const float4 f1 = *reinterpret_cast<const float4*>(rrow + 4);  // g1 b1 r2 g2
    const float4 f2 = *reinterpret_cast<const float4*>(rrow + 8);  // b2 r3 g3 b3

    // ---- reductions (packed f32x2 butterflies, width 16) ----
    const float rs = w0 * f0.x + w1 * f0.w + w2 * f1.z + w3 * f2.y;
    const float gs = w0 * f0.y + w1 * f1.x + w2 * f1.w + w3 * f2.z;
    const float bs = w0 * f0.z + w1 * f1.y + w2 * f2.x + w3 * f2.w;
    const float ds = w0 * m0 + w1 * m1 + w2 * m2 + w3 * m3;
    unsigned long long q0 = pack2(rs, gs);
    unsigned long long q1 = pack2(bs, ds);
    #pragma unroll
    for (int off = 8; off >= 1; off >>= 1) {
        q0 = addp(q0, __shfl_xor_sync(FULL, q0, off, 16));
        q1 = addp(q1, __shfl_xor_sync(FULL, q1, off, 16));
    }

    // total weight: exp(-ctot) is group-lane-15's T4
    const float wsum = 1.0f - __shfl_sync(FULL, T4, 15, 16);
    const float inv  = __fdividef(1.0f, wsum + 1e-6f);

    // normalized cdf at this lane's four positions
    const float cA = (1.0f - T1) * inv;   // cdf[4g]
    const float cB = (1.0f - T2) * inv;   // cdf[4g+1]
    const float cC = (1.0f - T3) * inv;   // cdf[4g+2]
    const float cD = (1.0f - T4) * inv;   // cdf[4g+3]
    float cprev = __shfl_up_sync(FULL, cD, 1, 16);   // cdf[4g-1]
    if (g == 0) cprev = 0.0f;

    // interval ends in fine-sample index space
    const int k1 = count_u(cA);
    const int k2 = count_u(cB);
    const int k3 = count_u(cC);
    const int k4 = count_u(cD);
    int kS = __shfl_up_sync(FULL, k4, 1, 16);        // = count_u(cprev)
    if (g == 0) kS = 0;

    // per-interval affine params: z = fmaf(u - cb, gcoef, mids[pc-1])
    const float d0 = cA - cprev;
    const float g0c = (g == 0) ? 0.0f : ((d0 < 1e-5f) ? delta : __fdividef(delta, d0));
    const float d1 = cB - cA;
    const float g1c = (d1 < 1e-5f) ? delta : __fdividef(delta, d1);
    const float d2 = cC - cB;
    const float g2c = (d2 < 1e-5f) ? delta : __fdividef(delta, d2);
    const float d3 = cD - cC;
    const float g3c = (d3 < 1e-5f) ? delta : __fdividef(delta, d3);

    float* zw = s_z[sub];
    unsigned char* Sw = reinterpret_cast<unsigned char*>(zw);  // byte S[128] aliases staging
    float2* pw = s_par[sub];

    // ---- S init (8B/lane) + params (2x STS.128/lane, conflict-free) ----
    reinterpret_cast<unsigned long long*>(zw)[g] = 0ULL;
    reinterpret_cast<float4*>(pw)[2 * g]     = make_float4(cprev, g0c, cA, g1c);
    reinterpret_cast<float4*>(pw)[2 * g + 1] = make_float4(cB,    g2c, cC, g3c);
    if (g == 15) pw[NS] = make_float2(0.0f, 0.0f);   // tail p=64: z = mids[63]
    __syncwarp();
    // interval-start marks (nonempty intervals have distinct starts; bytes 0..64)
    if (kS < k1) Sw[kS] = (unsigned char)(4 * g);
    if (k1 < k2) Sw[k1] = (unsigned char)(4 * g + 1);
    if (k2 < k3) Sw[k2] = (unsigned char)(4 * g + 2);
    if (k3 < k4) Sw[k3] = (unsigned char)(4 * g + 3);
    if (g == 15 && k4 < NF) Sw[k4] = (unsigned char)NS;   // tail interval start
    __syncwarp();

    // ---- p(k) = inclusive max-scan of byte S (8 bytes per lane) ----
    const unsigned long long wrd = reinterpret_cast<const unsigned long long*>(zw)[g];
    int sb[8];
    int run = 0;
    #pragma unroll
    for (int j = 0; j < 8; ++j) {
        run = max(run, (int)((wrd >> (8 * j)) & 0xFFULL));
        sb[j] = run;
    }
    int m = run;
    #pragma unroll
    for (int off = 1; off < 16; off <<= 1) {
        int t = __shfl_up_sync(FULL, m, off, 16);
        if (g >= off) m = max(m, t);
    }
    int pex = __shfl_up_sync(FULL, m, 1, 16);
    if (g == 0) pex = 0;
    __syncwarp();   // S fully consumed; staging reuse begins

    // ---- balanced fine pass: 8 samples per lane, branch-free ----
    const float ustep = 0.9f / 127.0f;
    const float base  = nr - 0.5f * delta;       // mids[pc-1] = fmaf(pc, delta, base)
    #pragma unroll
    for (int j = 0; j < 8; ++j) {
        const int k = 8 * g + j;
        const int p = max(pex, sb[j]);
        const int pc = min(max(p, 1), NS);       // clamp(p,1,64)
        const float2 pr = pw[p];
        const float u  = fmaf((float)k, ustep, 0.05f);
        const float mb = fmaf((float)pc, delta, base);
        zw[k + pc] = fmaf(u - pr.x, pr.y, mb);   // slot = k + clamp(p,1,64)
    }

    // ---- mids: slot = i + (# fine strictly before mid i) ----
    const int i0 = 4 * g;
    zw[(i0 == 0) ? 0 : (i0 + k1)] = m0;
    zw[i0 + 1 + k2] = m1;
    zw[i0 + 2 + k3] = m2;
    zw[i0 + 3 + k4] = m3;

    // ---- scalar outputs, distributed (all lanes hold reduced values) ----
    if (g < 5) {
        float rrs, rgs, rbs, rds;
        unpack2(q0, rrs, rgs);
        unpack2(q1, rbs, rds);
        if (g < 3) {
            const float val = (g == 0) ? rrs : (g == 1) ? rgs : rbs;
            rgb_out[(size_t)ray * 3 + g] = val;
        } else if (g == 3) {
            depth_out[ray] = __fdividef(rds, wsum + 1e-8f);
        } else {
            acc_out[ray] = wsum;
        }
    }
    } // ray < B

    // ---- block-level TMA bulk store: 16 contiguous ray rows (12 KB) ----
    __syncthreads();
    if (threadIdx.x == 0) {
        const size_t row0 = (size_t)blockIdx.x * RPB;
        // rows in this block that are valid (B % RPB == 0 in practice -> full)
        int nrays = B - (int)row0;
        if (nrays > RPB) nrays = RPB;
        if (nrays > 0) {
            asm volatile("fence.proxy.async.shared::cta;" ::: "memory");
            unsigned int saddr = (unsigned int)__cvta_generic_to_shared(&s_z[0][0]);
            float* gdst = zs_out + row0 * NC;
            const int bytes = nrays * NC * 4;
            asm volatile("cp.async.bulk.global.shared::cta.bulk_group [%0], [%1], %2;"
                         :: "l"(gdst), "r"(saddr), "r"(bytes) : "memory");
            asm volatile("cp.async.bulk.commit_group;" ::: "memory");
            asm volatile("cp.async.bulk.wait_group 0;" ::: "memory");
        }
    }
}

extern "C" void kernel_launch(void* const* d_in, const int* in_sizes, int n_in,
                              void* d_out, int out_size)
{
    const float* near_   = (const float*)d_in[0];
    const float* far_    = (const float*)d_in[1];
    const float* density = (const float*)d_in[2];
    const float* rgb     = (const float*)d_in[3];
    const int B = in_sizes[0];

    float* out   = (float*)d_out;
    float* zs    = out;                       // B * 192
    float* rgbo  = zs + (size_t)B * NC;       // B * 3
    float* depth = rgbo + (size_t)B * 3;      // B
    float* acc   = depth + B;                 // B

    const int blocks = (B + RPB - 1) / RPB;
    pdf_sampler_kernel<<<blocks, 256>>>(near_, far_, density, rgb,
                                        zs, rgbo, depth, acc, B);
}